// round 13
// baseline (speedup 1.0000x reference)
#include <cuda_runtime.h>
#include <cstdint>
#include <math.h>

#define PTS    8192
#define NB     4
#define NSETS  8                 // (batch, set): even = yhat, odd = y
#define NG     32                // 3D grid 32^3, cell 0.5
#define NCELL3 (NG * NG * NG)    // 32768
#define SLAB   (NG * NG)         // 1024 cells per z-slab
#define NSLAB  NG
#define GMIN   (-8.0f)
#define GINV   2.0f
#define PADP   64
#define NPAIR  (PADP + PTS / 2 + PADP)   // 4224 pairs
#define NRMAX  32                // light path: max rows
#define PAIRMAX 1024             // light path: max total pairs

__device__ float4 g_pp[NSETS][NPAIR * 2];     // {x0x1,y0y1},{z0z1,s0s1}
__device__ float4 g_q[NSETS][PTS];
__device__ int    g_hist[NSETS][NCELL3];      // zero at load; re-zeroed by scan1
__device__ int    g_start[NSETS][NCELL3];     // slab-local starts; post-scatter = slab-local ENDs
__device__ int    g_bsum[NSETS * NSLAB];      // per-slab totals
__device__ float  g_res[NSETS][PTS];
__device__ int    g_heavy[NSETS * PTS];
__device__ float  g_heavyr[NSETS * PTS];
__device__ int    g_hcount;
__device__ float  g_part[64];

__device__ __forceinline__ int snake_id(int bx, int by, int bz) {
    int iy = (bz & 1) ? (NG - 1 - by) : by;
    int ix = ((by + bz) & 1) ? (NG - 1 - bx) : bx;
    return (bz * NG + iy) * NG + ix;
}
__device__ __forceinline__ int cell_of(float x, float y, float z) {
    int bx = (int)fminf(fmaxf((x - GMIN) * GINV, 0.f), (float)(NG - 1));
    int by = (int)fminf(fmaxf((y - GMIN) * GINV, 0.f), (float)(NG - 1));
    int bz = (int)fminf(fmaxf((z - GMIN) * GINV, 0.f), (float)(NG - 1));
    return snake_id(bx, by, bz);
}

#define FMA_F32X2(d, a, b, c) \
    asm("fma.rn.f32x2 %0, %1, %2, %3;" : "=l"(d) : "l"(a), "l"(b), "l"(c))
#define UNPACK_F32X2(lo, hi, v) \
    asm("mov.b64 {%0, %1}, %2;" : "=f"(lo), "=f"(hi) : "l"(v))
__device__ __forceinline__ unsigned long long pack2f(float lo, float hi) {
    unsigned long long r;
    asm("mov.b64 %0, {%1, %2};" : "=l"(r) : "f"(lo), "f"(hi));
    return r;
}

__device__ __forceinline__ void proc_pair(
    const ulonglong2* __restrict__ pp, int j,
    unsigned long long q2x, unsigned long long q2y, unsigned long long q2z,
    float& bestA, float& bestB)
{
    ulonglong2 v0 = __ldg(pp + 2 * j);
    ulonglong2 v1 = __ldg(pp + 2 * j + 1);
    unsigned long long d;
    FMA_F32X2(d, q2z, v1.x, v1.y);
    FMA_F32X2(d, q2y, v0.y, d);
    FMA_F32X2(d, q2x, v0.x, d);
    float lo, hi;
    UNPACK_F32X2(lo, hi, d);
    bestA = fminf(bestA, lo);
    bestB = fminf(bestB, hi);
}

// ---- launch 1: histogram (g_hist zero at load; scan1 re-zeroes each run) --
__global__ __launch_bounds__(512)
void hist_kernel(const float* __restrict__ yhat, const float* __restrict__ y)
{
    int gid = blockIdx.x * 512 + threadIdx.x;
    int g = gid >> 13, i = gid & 8191;
    const float* src = ((g & 1) ? y : yhat) + (size_t)(g >> 1) * PTS * 3;
    float x = src[3 * i], yy = src[3 * i + 1], z = src[3 * i + 2];
    atomicAdd(&g_hist[g][cell_of(x, yy, z)], 1);
}

// ---- launch 2: per-slab exclusive scan -> slab-LOCAL starts; totals to
// g_bsum; zero hist back; pads; hcount reset. 256 blocks = 8 sets x 32 slabs.
__global__ __launch_bounds__(128)
void scan1_kernel()
{
    __shared__ int wsum[4];
    const int blk = blockIdx.x, s = blk >> 5, slab = blk & 31;
    const int t = threadIdx.x, lane = t & 31, warp = t >> 5;
    int4* h4 = (int4*)&g_hist[s][slab * SLAB];
    int4 a = h4[2 * t], b = h4[2 * t + 1];
    int4 z4 = make_int4(0, 0, 0, 0);
    h4[2 * t] = z4; h4[2 * t + 1] = z4;
    int tot = a.x + a.y + a.z + a.w + b.x + b.y + b.z + b.w;
    int inc = tot;
#pragma unroll
    for (int o = 1; o < 32; o <<= 1) {
        int u = __shfl_up_sync(0xffffffffu, inc, o);
        if (lane >= o) inc += u;
    }
    if (lane == 31) wsum[warp] = inc;
    __syncthreads();
    int woff = 0;
    for (int w = 0; w < 4; ++w) {
        int v = wsum[w];
        if (w < warp) woff += v;
    }
    int run = inc - tot + woff;
    int4 o1, o2;
    o1.x = run;       o1.y = run + a.x; o1.z = o1.y + a.y; o1.w = o1.z + a.z;
    run = o1.w + a.w;
    o2.x = run;       o2.y = run + b.x; o2.z = o2.y + b.y; o2.w = o2.z + b.z;
    run = o2.w + b.w;
    int4* s4 = (int4*)&g_start[s][slab * SLAB];
    s4[2 * t] = o1; s4[2 * t + 1] = o2;
    if (t == 127) g_bsum[s * NSLAB + slab] = run;
    if (blk == 0 && t == 0) g_hcount = 0;
    if (slab == 0 && t < PADP) {
        g_pp[s][2 * t]     = make_float4(0.f, 0.f, 0.f, 0.f);
        g_pp[s][2 * t + 1] = make_float4(0.f, 0.f, 3.0e38f, 3.0e38f);
        int o = PADP + PTS / 2 + t;
        g_pp[s][2 * o]     = make_float4(0.f, 0.f, 0.f, 0.f);
        g_pp[s][2 * o + 1] = make_float4(0.f, 0.f, 3.0e38f, 3.0e38f);
    }
}

// ---- launch 3: scatter. atomicAdd on g_start: afterwards g_start[c] =
// slab-local END of cell c. Within-cell order nondeterministic; exact-min
// output is order-independent.
__global__ __launch_bounds__(512)
void scatter_kernel(const float* __restrict__ yhat, const float* __restrict__ y)
{
    __shared__ int sb[NSLAB], off[NSLAB];
    const int bid = blockIdx.x;           // 128 blocks, 16 per set
    const int g = bid >> 4;
    const int t = threadIdx.x;
    if (t < NSLAB) sb[t] = g_bsum[g * NSLAB + t];
    __syncthreads();
    if (t < NSLAB) {
        int p = 0;
        for (int k = 0; k < t; ++k) p += sb[k];
        off[t] = p;
    }
    __syncthreads();

    const float* src = ((g & 1) ? y : yhat) + (size_t)(g >> 1) * PTS * 3;
    int i = (bid & 15) * 512 + t;
    float x = src[3 * i], yy = src[3 * i + 1], z = src[3 * i + 2];
    int cell = cell_of(x, yy, z);
    int pos = off[cell / SLAB] + atomicAdd(&g_start[g][cell], 1);
    float s = x * x + yy * yy + z * z;
    int pj = PADP + (pos >> 1), sl = pos & 1;
    float* pA = (float*)&g_pp[g][2 * pj];
    pA[sl] = x; pA[2 + sl] = yy; pA[4 + sl] = z; pA[6 + sl] = s;
    g_q[g][pos] = make_float4(x, yy, z, s);
}

// run begin of cell idx (slab-local, post-scatter semantics)
__device__ __forceinline__ int run_begin(const int* __restrict__ st, int idx) {
    return ((idx & (SLAB - 1)) == 0) ? 0 : __ldg(st + idx - 1);
}

// ---- launch 4 (ncu capture slot): search ----------------------------------
// Light: NR<=NRMAX rows AND <=PAIRMAX pairs -> broadcast row scan.
// Else defer query (with its phase-1 radius) to heavy_kernel. Both exact.
// Query->warp map is INTERLEAVED (slot = warp*64 + sub) so each block's 4
// warps sample the sorted order evenly -> balanced block costs.
__global__ __launch_bounds__(128)
void search_kernel()
{
    __shared__ int off[NSLAB + 1];

    const int bid = blockIdx.x;          // 512 blocks; 64 per set
    const int qset = bid >> 6;
    const int pset = qset ^ 1;
    const int t = threadIdx.x, warp = t >> 5, lane = t & 31;

    if (t < NSLAB) {
        int v = g_bsum[pset * NSLAB + t];
        int inc = v;
#pragma unroll
        for (int o = 1; o < 32; o <<= 1) {
            int u = __shfl_up_sync(0xffffffffu, inc, o);
            if (t >= o) inc += u;
        }
        off[t] = inc - v;
        if (t == 31) off[NSLAB] = inc;
    }
    __syncthreads();

    const int qi = (warp * 64 + (bid & 63)) * 32 + lane;   // interleaved
    float4 q = __ldg(&g_q[qset][qi]);
    const float qx = q.x, qy = q.y, qz = q.z, sqq = q.w;
    const unsigned long long q2x = pack2f(-2.f * qx, -2.f * qx);
    const unsigned long long q2y = pack2f(-2.f * qy, -2.f * qy);
    const unsigned long long q2z = pack2f(-2.f * qz, -2.f * qz);

    const int* st = &g_start[pset][0];

    float cx = __shfl_sync(0xffffffffu, qx, 16);
    float cy = __shfl_sync(0xffffffffu, qy, 16);
    float cz = __shfl_sync(0xffffffffu, qz, 16);
    int cellA = cell_of(cx, cy, cz);
    const int k0 = off[cellA / SLAB] + run_begin(st, cellA);
    const int k0p = PADP + (k0 >> 1);

    float bestA = 3.0e38f, bestB = 3.0e38f;
    const ulonglong2* pp = (const ulonglong2*)&g_pp[pset][0];

    // phase 1: fixed 32 pairs (64 snake-adjacent points) around anchor
#pragma unroll
    for (int jj = 0; jj < 32; ++jj)
        proc_pair(pp, k0p - 8 + jj, q2x, q2y, q2z, bestA, bestB);

    // per-lane radius; warp-union box for the light path
    float rl = sqrtf(fmaxf(fminf(bestA, bestB) + sqq, 0.f));
    float xmn = qx - rl, xmx = qx + rl;
    float ymn = qy - rl, ymx = qy + rl;
    float zmn = qz - rl, zmx = qz + rl;
#pragma unroll
    for (int o = 16; o > 0; o >>= 1) {
        xmn = fminf(xmn, __shfl_xor_sync(0xffffffffu, xmn, o));
        xmx = fmaxf(xmx, __shfl_xor_sync(0xffffffffu, xmx, o));
        ymn = fminf(ymn, __shfl_xor_sync(0xffffffffu, ymn, o));
        ymx = fmaxf(ymx, __shfl_xor_sync(0xffffffffu, ymx, o));
        zmn = fminf(zmn, __shfl_xor_sync(0xffffffffu, zmn, o));
        zmx = fmaxf(zmx, __shfl_xor_sync(0xffffffffu, zmx, o));
    }
    int bx0 = (int)fminf(fmaxf((xmn - GMIN) * GINV, 0.f), (float)(NG - 1));
    int bx1 = (int)fminf(fmaxf((xmx - GMIN) * GINV, 0.f), (float)(NG - 1));
    int by0 = (int)fminf(fmaxf((ymn - GMIN) * GINV, 0.f), (float)(NG - 1));
    int by1 = (int)fminf(fmaxf((ymx - GMIN) * GINV, 0.f), (float)(NG - 1));
    int bz0 = (int)fminf(fmaxf((zmn - GMIN) * GINV, 0.f), (float)(NG - 1));
    int bz1 = (int)fminf(fmaxf((zmx - GMIN) * GINV, 0.f), (float)(NG - 1));

    const int NYb = by1 - by0 + 1;
    const int NR  = NYb * (bz1 - bz0 + 1);

    bool heavy = (NR > NRMAX);
    int2 bnd = make_int2(0, 0);
    if (!heavy) {
        if (lane < NR) {
            int by = by0 + lane % NYb;
            int bz = bz0 + lane / NYb;
            int iy  = (bz & 1) ? (NG - 1 - by) : by;
            int dir = (by + bz) & 1;
            int ic0 = dir ? (NG - 1 - bx1) : bx0;
            int ic1 = dir ? (NG - 1 - bx0) : bx1;
            int rowbase = (bz * NG + iy) * NG;
            int is = off[bz] + run_begin(st, rowbase + ic0);
            int ie = off[bz] + __ldg(st + rowbase + ic1);
            bnd = make_int2(PADP + (is >> 1), PADP + ((ie + 1) >> 1));
        }
        int np = bnd.y - bnd.x;
#pragma unroll
        for (int o = 16; o > 0; o >>= 1)
            np += __shfl_xor_sync(0xffffffffu, np, o);
        heavy = (np > PAIRMAX);
    }

    if (heavy) {
        int base;
        if (lane == 0) base = atomicAdd(&g_hcount, 32);
        base = __shfl_sync(0xffffffffu, base, 0);
        g_heavy[base + lane]  = (qset << 13) | qi;
        g_heavyr[base + lane] = rl;
        return;
    }

    for (int rr = 0; rr < NR; ++rr) {
        int jb = __shfl_sync(0xffffffffu, bnd.x, rr);
        int je = __shfl_sync(0xffffffffu, bnd.y, rr);
        for (int j = jb; j < je; j += 4) {   // overshoot <=3 pairs: safe
            proc_pair(pp, j,     q2x, q2y, q2z, bestA, bestB);
            proc_pair(pp, j + 1, q2x, q2y, q2z, bestA, bestB);
            proc_pair(pp, j + 2, q2x, q2y, q2z, bestA, bestB);
            proc_pair(pp, j + 3, q2x, q2y, q2z, bestA, bestB);
        }
    }

    g_res[qset][qi] = fmaxf(fminf(bestA, bestB) + sqq, 0.f);
}

// ---- launch 5: heavy. One warp per deferred query. Re-tighten r by
// scanning 32 pairs around the query's OWN cell, then scan its own box:
// rows broadcast via shfl, LANES STRIDE WITHIN EACH ROW (dense rows use all
// 32 lanes). Butterfly min. Exact.
__global__ __launch_bounds__(128)
void heavy_kernel()
{
    const int gw = (blockIdx.x * 128 + threadIdx.x) >> 5;
    const int lane = threadIdx.x & 31;
    const int nw = (gridDim.x * 128) >> 5;
    const int H = g_hcount;

    for (int h = gw; h < H; h += nw) {
        int code = g_heavy[h];
        float r0 = g_heavyr[h];
        int qset = code >> 13, qi = code & 8191, pset = qset ^ 1;
        float4 q = __ldg(&g_q[qset][qi]);
        const unsigned long long q2x = pack2f(-2.f * q.x, -2.f * q.x);
        const unsigned long long q2y = pack2f(-2.f * q.y, -2.f * q.y);
        const unsigned long long q2z = pack2f(-2.f * q.z, -2.f * q.z);
        const ulonglong2* pp = (const ulonglong2*)&g_pp[pset][0];
        const int* st = &g_start[pset][0];

        // lane-held exclusive slab offsets
        int bs = __ldg(&g_bsum[pset * NSLAB + lane]);
        int offl = bs;
#pragma unroll
        for (int o = 1; o < 32; o <<= 1) {
            int u = __shfl_up_sync(0xffffffffu, offl, o);
            if (lane >= o) offl += u;
        }
        offl -= bs;

        float bestA = 3.0e38f, bestB = 3.0e38f;

        // re-tighten: 32 pairs around the query's OWN cell, lane-parallel
        {
            int cellQ = cell_of(q.x, q.y, q.z);
            int offq = __shfl_sync(0xffffffffu, offl, cellQ / SLAB);
            int kq = PADP + ((offq + run_begin(st, cellQ)) >> 1);
            proc_pair(pp, kq - 8 + lane, q2x, q2y, q2z, bestA, bestB);
        }
        {
            float ba = bestA, bb = bestB;
#pragma unroll
            for (int o = 16; o > 0; o >>= 1) {
                ba = fminf(ba, __shfl_xor_sync(0xffffffffu, ba, o));
                bb = fminf(bb, __shfl_xor_sync(0xffffffffu, bb, o));
            }
            float r1 = sqrtf(fmaxf(fminf(ba, bb) + q.w, 0.f));
            r0 = fminf(r0, r1);   // any upper bound on NN dist keeps box exact
        }

        int bx0 = (int)fminf(fmaxf((q.x - r0 - GMIN) * GINV, 0.f), (float)(NG - 1));
        int bx1 = (int)fminf(fmaxf((q.x + r0 - GMIN) * GINV, 0.f), (float)(NG - 1));
        int by0 = (int)fminf(fmaxf((q.y - r0 - GMIN) * GINV, 0.f), (float)(NG - 1));
        int by1 = (int)fminf(fmaxf((q.y + r0 - GMIN) * GINV, 0.f), (float)(NG - 1));
        int bz0 = (int)fminf(fmaxf((q.z - r0 - GMIN) * GINV, 0.f), (float)(NG - 1));
        int bz1 = (int)fminf(fmaxf((q.z + r0 - GMIN) * GINV, 0.f), (float)(NG - 1));
        int NYb = by1 - by0 + 1;
        int NR  = NYb * (bz1 - bz0 + 1);

        for (int base = 0; base < NR; base += 32) {
            int rr = base + lane;
            int2 bnd = make_int2(0, 0);
            if (rr < NR) {
                int by = by0 + rr % NYb;
                int bz = bz0 + rr / NYb;
                int offbz = __shfl_sync(0xffffffffu, offl, bz);
                int iy  = (bz & 1) ? (NG - 1 - by) : by;
                int dir = (by + bz) & 1;
                int ic0 = dir ? (NG - 1 - bx1) : bx0;
                int ic1 = dir ? (NG - 1 - bx0) : bx1;
                int rowbase = (bz * NG + iy) * NG;
                int is = offbz + run_begin(st, rowbase + ic0);
                int ie = offbz + __ldg(st + rowbase + ic1);
                bnd = make_int2(PADP + (is >> 1), PADP + ((ie + 1) >> 1));
            } else {
                int offbz = __shfl_sync(0xffffffffu, offl, 0);  // keep shfl uniform
                (void)offbz;
            }
            int nrows = min(32, NR - base);
            for (int rq = 0; rq < nrows; ++rq) {
                int jb = __shfl_sync(0xffffffffu, bnd.x, rq);
                int je = __shfl_sync(0xffffffffu, bnd.y, rq);
                for (int j = jb + lane; j < je; j += 32)   // lanes stride row
                    proc_pair(pp, j, q2x, q2y, q2z, bestA, bestB);
            }
        }
        float best = fminf(bestA, bestB);
#pragma unroll
        for (int o = 16; o > 0; o >>= 1)
            best = fminf(best, __shfl_xor_sync(0xffffffffu, best, o));
        if (lane == 0)
            g_res[qset][qi] = fmaxf(best + q.w, 0.f);
    }
}

// ---- launches 6+7: reduction ----------------------------------------------
__global__ void reduce_partial_kernel()
{
    const int t = threadIdx.x, bid = blockIdx.x;
    const float* r = (const float*)g_res;
    float s = 0.f;
#pragma unroll
    for (int k = 0; k < 4; ++k)
        s += r[bid * 1024 + k * 256 + t];
#pragma unroll
    for (int o = 16; o > 0; o >>= 1)
        s += __shfl_down_sync(0xffffffffu, s, o);
    __shared__ float sh[8];
    if ((t & 31) == 0) sh[t >> 5] = s;
    __syncthreads();
    if (t == 0) {
        float v = 0.f;
#pragma unroll
        for (int w = 0; w < 8; ++w) v += sh[w];
        g_part[bid] = v;
    }
}

__global__ void final_kernel(float* __restrict__ out)
{
    const int t = threadIdx.x;   // 32
    double s = (double)g_part[t] + (double)g_part[t + 32];
#pragma unroll
    for (int o = 16; o > 0; o >>= 1)
        s += __shfl_down_sync(0xffffffffu, s, o);
    if (t == 0)
        out[0] = (float)sqrt(0.5 * s / (double)(NB * PTS));
}

extern "C" void kernel_launch(void* const* d_in, const int* in_sizes, int n_in,
                              void* d_out, int out_size)
{
    const float* yhat = (const float*)d_in[0];   // [B, N, 3]
    const float* y    = (const float*)d_in[1];   // [B, M, 3]
    (void)in_sizes; (void)n_in; (void)out_size;

    hist_kernel<<<128, 512>>>(yhat, y);          // 1
    scan1_kernel<<<256, 128>>>();                // 2
    scatter_kernel<<<128, 512>>>(yhat, y);       // 3
    search_kernel<<<512, 128>>>();               // 4  <- ncu capture slot
    heavy_kernel<<<512, 128>>>();                // 5
    reduce_partial_kernel<<<64, 256>>>();        // 6
    final_kernel<<<1, 32>>>((float*)d_out);      // 7
}

// round 14
// speedup vs baseline: 1.5719x; 1.5719x over previous
#include <cuda_runtime.h>
#include <cstdint>
#include <math.h>

#define PTS    8192
#define NB     4
#define NSETS  8                 // (batch, set): even = yhat, odd = y
#define NG     32                // 3D grid 32^3, cell 0.5
#define NCELL3 (NG * NG * NG)    // 32768
#define SLAB   (NG * NG)         // 1024 cells per z-slab
#define NSLAB  NG
#define GMIN   (-8.0f)
#define GINV   2.0f
#define PADP   64
#define NPAIR  (PADP + PTS / 2 + PADP)   // 4224 pairs
#define SMEM_PAIR_BYTES (NPAIR * 2 * 16) // 135168 B

__device__ float4 g_pp[NSETS][NPAIR * 2];     // {x0x1,y0y1},{z0z1,s0s1}
__device__ float4 g_q[NSETS][PTS];
__device__ int    g_hist[NSETS][NCELL3];      // zero at load; re-zeroed by scan1
__device__ int    g_start[NSETS][NCELL3];     // slab-local starts; post-scatter = ENDs
__device__ int    g_bsum[NSETS * NSLAB];      // per-slab totals
__device__ float  g_res[NSETS][PTS];
__device__ float  g_part[64];

__device__ __forceinline__ int snake_id(int bx, int by, int bz) {
    int iy = (bz & 1) ? (NG - 1 - by) : by;
    int ix = ((by + bz) & 1) ? (NG - 1 - bx) : bx;
    return (bz * NG + iy) * NG + ix;
}
__device__ __forceinline__ int cell_of(float x, float y, float z) {
    int bx = (int)fminf(fmaxf((x - GMIN) * GINV, 0.f), (float)(NG - 1));
    int by = (int)fminf(fmaxf((y - GMIN) * GINV, 0.f), (float)(NG - 1));
    int bz = (int)fminf(fmaxf((z - GMIN) * GINV, 0.f), (float)(NG - 1));
    return snake_id(bx, by, bz);
}

#define FMA_F32X2(d, a, b, c) \
    asm("fma.rn.f32x2 %0, %1, %2, %3;" : "=l"(d) : "l"(a), "l"(b), "l"(c))
#define UNPACK_F32X2(lo, hi, v) \
    asm("mov.b64 {%0, %1}, %2;" : "=f"(lo), "=f"(hi) : "l"(v))
__device__ __forceinline__ unsigned long long pack2f(float lo, float hi) {
    unsigned long long r;
    asm("mov.b64 %0, {%1, %2};" : "=l"(r) : "f"(lo), "f"(hi));
    return r;
}

// ---- launch 1: histogram ---------------------------------------------------
__global__ __launch_bounds__(512)
void hist_kernel(const float* __restrict__ yhat, const float* __restrict__ y)
{
    int gid = blockIdx.x * 512 + threadIdx.x;
    int g = gid >> 13, i = gid & 8191;
    const float* src = ((g & 1) ? y : yhat) + (size_t)(g >> 1) * PTS * 3;
    float x = src[3 * i], yy = src[3 * i + 1], z = src[3 * i + 2];
    atomicAdd(&g_hist[g][cell_of(x, yy, z)], 1);
}

// ---- launch 2: per-slab scan -> slab-local starts; totals; zero hist back --
__global__ __launch_bounds__(128)
void scan1_kernel()
{
    __shared__ int wsum[4];
    const int blk = blockIdx.x, s = blk >> 5, slab = blk & 31;
    const int t = threadIdx.x, lane = t & 31, warp = t >> 5;
    int4* h4 = (int4*)&g_hist[s][slab * SLAB];
    int4 a = h4[2 * t], b = h4[2 * t + 1];
    int4 z4 = make_int4(0, 0, 0, 0);
    h4[2 * t] = z4; h4[2 * t + 1] = z4;
    int tot = a.x + a.y + a.z + a.w + b.x + b.y + b.z + b.w;
    int inc = tot;
#pragma unroll
    for (int o = 1; o < 32; o <<= 1) {
        int u = __shfl_up_sync(0xffffffffu, inc, o);
        if (lane >= o) inc += u;
    }
    if (lane == 31) wsum[warp] = inc;
    __syncthreads();
    int woff = 0;
    for (int w = 0; w < 4; ++w) {
        int v = wsum[w];
        if (w < warp) woff += v;
    }
    int run = inc - tot + woff;
    int4 o1, o2;
    o1.x = run;       o1.y = run + a.x; o1.z = o1.y + a.y; o1.w = o1.z + a.z;
    run = o1.w + a.w;
    o2.x = run;       o2.y = run + b.x; o2.z = o2.y + b.y; o2.w = o2.z + b.z;
    run = o2.w + b.w;
    int4* s4 = (int4*)&g_start[s][slab * SLAB];
    s4[2 * t] = o1; s4[2 * t + 1] = o2;
    if (t == 127) g_bsum[s * NSLAB + slab] = run;
    if (slab == 0 && t < PADP) {
        g_pp[s][2 * t]     = make_float4(0.f, 0.f, 0.f, 0.f);
        g_pp[s][2 * t + 1] = make_float4(0.f, 0.f, 3.0e38f, 3.0e38f);
        int o = PADP + PTS / 2 + t;
        g_pp[s][2 * o]     = make_float4(0.f, 0.f, 0.f, 0.f);
        g_pp[s][2 * o + 1] = make_float4(0.f, 0.f, 3.0e38f, 3.0e38f);
    }
}

// ---- launch 3: scatter; post-scatter g_start[c] = slab-local END of c ------
__global__ __launch_bounds__(512)
void scatter_kernel(const float* __restrict__ yhat, const float* __restrict__ y)
{
    __shared__ int sb[NSLAB], off[NSLAB];
    const int bid = blockIdx.x;           // 128 blocks, 16 per set
    const int g = bid >> 4;
    const int t = threadIdx.x;
    if (t < NSLAB) sb[t] = g_bsum[g * NSLAB + t];
    __syncthreads();
    if (t < NSLAB) {
        int p = 0;
        for (int k = 0; k < t; ++k) p += sb[k];
        off[t] = p;
    }
    __syncthreads();

    const float* src = ((g & 1) ? y : yhat) + (size_t)(g >> 1) * PTS * 3;
    int i = (bid & 15) * 512 + t;
    float x = src[3 * i], yy = src[3 * i + 1], z = src[3 * i + 2];
    int cell = cell_of(x, yy, z);
    int pos = off[cell / SLAB] + atomicAdd(&g_start[g][cell], 1);
    float s = x * x + yy * yy + z * z;
    int pj = PADP + (pos >> 1), sl = pos & 1;
    float* pA = (float*)&g_pp[g][2 * pj];
    pA[sl] = x; pA[2 + sl] = yy; pA[4 + sl] = z; pA[6 + sl] = s;
    g_q[g][pos] = make_float4(x, yy, z, s);
}

// run begin of cell idx (slab-local, post-scatter semantics)
__device__ __forceinline__ int run_begin(const int* __restrict__ st, int idx) {
    return ((idx & (SLAB - 1)) == 0) ? 0 : __ldg(st + idx - 1);
}

// smem pair processing: all lanes load the SAME address -> LDS broadcast,
// conflict-free, feeding f32x2 FMA directly.
__device__ __forceinline__ void proc_pair_s(
    const ulonglong2* pp, int j,
    unsigned long long q2x, unsigned long long q2y, unsigned long long q2z,
    float& bestA, float& bestB)
{
    ulonglong2 v0 = pp[2 * j];       // (x0,x1)(y0,y1)
    ulonglong2 v1 = pp[2 * j + 1];   // (z0,z1)(s0,s1)
    unsigned long long d;
    FMA_F32X2(d, q2z, v1.x, v1.y);
    FMA_F32X2(d, q2y, v0.y, d);
    FMA_F32X2(d, q2x, v0.x, d);
    float lo, hi;
    UNPACK_F32X2(lo, hi, d);
    bestA = fminf(bestA, lo);
    bestB = fminf(bestB, hi);
}

// ---- launch 4 (ncu capture slot): search -----------------------------------
// Whole pset pair array is SMEM-RESIDENT (135KB, 1 block/SM, 16 warps).
// Phase 1 (64 snake-adjacent pts) -> per-lane radius -> warp-union cell box
// -> chunked row scan (32 row bounds prefetched per chunk, broadcast
// consume). No heavy path: worst case is bounded by the full smem array.
// Exact: any point improving lane l lies within r_l of q_l per axis.
__global__ __launch_bounds__(512)
void search_kernel()
{
    extern __shared__ float4 spp4[];       // NPAIR*2
    __shared__ int off[NSLAB + 1];

    const int bid = blockIdx.x;            // 128 blocks; 16 per set
    const int qset = bid >> 4;
    const int pset = qset ^ 1;
    const int sub = bid & 15;
    const int t = threadIdx.x, warp = t >> 5, lane = t & 31;

    // cooperative copy of the candidate set into smem
    const float4* gp = &g_pp[pset][0];
    for (int i = t; i < NPAIR * 2; i += 512)
        spp4[i] = __ldg(gp + i);

    if (t < NSLAB) {
        int v = g_bsum[pset * NSLAB + t];
        int inc = v;
#pragma unroll
        for (int o = 1; o < 32; o <<= 1) {
            int u = __shfl_up_sync(0xffffffffu, inc, o);
            if (t >= o) inc += u;
        }
        off[t] = inc - v;
        if (t == 31) off[NSLAB] = inc;
    }
    __syncthreads();

    const ulonglong2* pp = (const ulonglong2*)spp4;
    const int* st = &g_start[pset][0];

    // interleaved assignment: block's 16 warps sample the snake order evenly
    const int qi = (warp * 16 + sub) * 32 + lane;
    float4 q = __ldg(&g_q[qset][qi]);
    const float qx = q.x, qy = q.y, qz = q.z, sqq = q.w;
    const unsigned long long q2x = pack2f(-2.f * qx, -2.f * qx);
    const unsigned long long q2y = pack2f(-2.f * qy, -2.f * qy);
    const unsigned long long q2z = pack2f(-2.f * qz, -2.f * qz);

    float cx = __shfl_sync(0xffffffffu, qx, 16);
    float cy = __shfl_sync(0xffffffffu, qy, 16);
    float cz = __shfl_sync(0xffffffffu, qz, 16);
    int cellA = cell_of(cx, cy, cz);
    const int k0 = off[cellA / SLAB] + run_begin(st, cellA);
    const int k0p = PADP + (k0 >> 1);

    float bestA = 3.0e38f, bestB = 3.0e38f;

    // phase 1: fixed 32 pairs (64 snake-adjacent points) around anchor
#pragma unroll
    for (int jj = 0; jj < 32; ++jj)
        proc_pair_s(pp, k0p - 8 + jj, q2x, q2y, q2z, bestA, bestB);

    // per-lane radius -> warp-union cell box
    float rl = sqrtf(fmaxf(fminf(bestA, bestB) + sqq, 0.f));
    float xmn = qx - rl, xmx = qx + rl;
    float ymn = qy - rl, ymx = qy + rl;
    float zmn = qz - rl, zmx = qz + rl;
#pragma unroll
    for (int o = 16; o > 0; o >>= 1) {
        xmn = fminf(xmn, __shfl_xor_sync(0xffffffffu, xmn, o));
        xmx = fmaxf(xmx, __shfl_xor_sync(0xffffffffu, xmx, o));
        ymn = fminf(ymn, __shfl_xor_sync(0xffffffffu, ymn, o));
        ymx = fmaxf(ymx, __shfl_xor_sync(0xffffffffu, ymx, o));
        zmn = fminf(zmn, __shfl_xor_sync(0xffffffffu, zmn, o));
        zmx = fmaxf(zmx, __shfl_xor_sync(0xffffffffu, zmx, o));
    }
    int bx0 = (int)fminf(fmaxf((xmn - GMIN) * GINV, 0.f), (float)(NG - 1));
    int bx1 = (int)fminf(fmaxf((xmx - GMIN) * GINV, 0.f), (float)(NG - 1));
    int by0 = (int)fminf(fmaxf((ymn - GMIN) * GINV, 0.f), (float)(NG - 1));
    int by1 = (int)fminf(fmaxf((ymx - GMIN) * GINV, 0.f), (float)(NG - 1));
    int bz0 = (int)fminf(fmaxf((zmn - GMIN) * GINV, 0.f), (float)(NG - 1));
    int bz1 = (int)fminf(fmaxf((zmx - GMIN) * GINV, 0.f), (float)(NG - 1));

    const int NYb = by1 - by0 + 1;
    const int NR  = NYb * (bz1 - bz0 + 1);

    // chunked row scan: 32 row bounds fetched lane-parallel, then consumed
    // via shfl broadcast; pair loop overshoots to x2 (pads / rescans safe:
    // idempotent min, pad s = 3e38 never wins)
    for (int cb = 0; cb < NR; cb += 32) {
        int ri = cb + lane;
        int2 bnd = make_int2(0, 0);
        if (ri < NR) {
            int by = by0 + ri % NYb;
            int bz = bz0 + ri / NYb;
            int iy  = (bz & 1) ? (NG - 1 - by) : by;
            int dir = (by + bz) & 1;
            int ic0 = dir ? (NG - 1 - bx1) : bx0;
            int ic1 = dir ? (NG - 1 - bx0) : bx1;
            int rowbase = (bz * NG + iy) * NG;
            int is = off[bz] + run_begin(st, rowbase + ic0);
            int ie = off[bz] + __ldg(st + rowbase + ic1);
            bnd = make_int2(PADP + (is >> 1), PADP + ((ie + 1) >> 1));
        }
        int nrows = min(32, NR - cb);
        for (int rr = 0; rr < nrows; ++rr) {
            int jb = __shfl_sync(0xffffffffu, bnd.x, rr);
            int je = __shfl_sync(0xffffffffu, bnd.y, rr);
            for (int j = jb; j < je; j += 2) {
                proc_pair_s(pp, j,     q2x, q2y, q2z, bestA, bestB);
                proc_pair_s(pp, j + 1, q2x, q2y, q2z, bestA, bestB);
            }
        }
    }

    g_res[qset][qi] = fmaxf(fminf(bestA, bestB) + sqq, 0.f);
}

// ---- launches 5+6: reduction ------------------------------------------------
__global__ void reduce_partial_kernel()
{
    const int t = threadIdx.x, bid = blockIdx.x;
    const float* r = (const float*)g_res;
    float s = 0.f;
#pragma unroll
    for (int k = 0; k < 4; ++k)
        s += r[bid * 1024 + k * 256 + t];
#pragma unroll
    for (int o = 16; o > 0; o >>= 1)
        s += __shfl_down_sync(0xffffffffu, s, o);
    __shared__ float sh[8];
    if ((t & 31) == 0) sh[t >> 5] = s;
    __syncthreads();
    if (t == 0) {
        float v = 0.f;
#pragma unroll
        for (int w = 0; w < 8; ++w) v += sh[w];
        g_part[bid] = v;
    }
}

__global__ void final_kernel(float* __restrict__ out)
{
    const int t = threadIdx.x;   // 32
    double s = (double)g_part[t] + (double)g_part[t + 32];
#pragma unroll
    for (int o = 16; o > 0; o >>= 1)
        s += __shfl_down_sync(0xffffffffu, s, o);
    if (t == 0)
        out[0] = (float)sqrt(0.5 * s / (double)(NB * PTS));
}

extern "C" void kernel_launch(void* const* d_in, const int* in_sizes, int n_in,
                              void* d_out, int out_size)
{
    const float* yhat = (const float*)d_in[0];   // [B, N, 3]
    const float* y    = (const float*)d_in[1];   // [B, M, 3]
    (void)in_sizes; (void)n_in; (void)out_size;

    cudaFuncSetAttribute(search_kernel,
                         cudaFuncAttributeMaxDynamicSharedMemorySize,
                         SMEM_PAIR_BYTES);

    hist_kernel<<<128, 512>>>(yhat, y);              // 1
    scan1_kernel<<<256, 128>>>();                    // 2
    scatter_kernel<<<128, 512>>>(yhat, y);           // 3
    search_kernel<<<128, 512, SMEM_PAIR_BYTES>>>();  // 4 <- ncu capture slot
    reduce_partial_kernel<<<64, 256>>>();            // 5
    final_kernel<<<1, 32>>>((float*)d_out);          // 6
}